// round 13
// baseline (speedup 1.0000x reference)
#include <cuda_runtime.h>
#include <cuda_bf16.h>

// Shapes fixed by reference setup_inputs
#define FF 2
#define BB 64
#define SS 512
#define DD 768
#define ROWB (DD * 4)            // 3072 bytes per row
#define NPAIR (FF * BB)          // 128
#define NROWS (NPAIR * SS)       // 65536 flattened rows
#define GRIDN 444                // 3 x 148 -> exactly 3 CTAs per SM, one wave

#define DEPTH 3
#define BUFS_BYTES (8 * DEPTH * ROWB)    // 73728
#define CTRL_OFF   BUFS_BYTES
#define SMEM_BYTES (BUFS_BYTES + 2048)   // 75776 (x3 = 227328 B/SM, same as R11)

__device__ float        g_partial[GRIDN * 2];
__device__ unsigned int g_count = 0;

__device__ __forceinline__ void cp16(unsigned sdst, const void* gsrc) {
    asm volatile("cp.async.cg.shared.global [%0], [%1], 16;" :: "r"(sdst), "l"(gsrc));
}

__global__ __launch_bounds__(256) void nl_fused_kernel(
    const float* __restrict__ tok,
    const float* __restrict__ sent,
    const int* __restrict__ mask,
    float* __restrict__ out)
{
    extern __shared__ char smem[];
    const int c    = blockIdx.x;
    const int tid  = threadIdx.x;
    const int warp = tid >> 5;
    const int lane = tid & 31;

    short* s_idx  = (short*)(smem + CTRL_OFF);          // [256]
    int*   s_cnt  = (int*)(smem + CTRL_OFF + 512);      // [8]
    float* s_acc  = (float*)(smem + CTRL_OFF + 576);    // [8]
    float* s_val  = (float*)(smem + CTRL_OFF + 640);    // [NPAIR]
    int*   s_flag = (int*)(smem + CTRL_OFF + 1536);

    // Equal row-range for this CTA over the flattened 65536 rows (~148 rows).
    const int lo = (int)(((long long)c * NROWS) / GRIDN);
    const int hi = (int)(((long long)(c + 1) * NROWS) / GRIDN);
    const int p0 = lo >> 9;
    const int p1 = (hi - 1) >> 9;
    const int nseg = (p1 > p0) ? 2 : 1;

    const unsigned buf_base =
        (unsigned)__cvta_generic_to_shared(smem) + warp * (DEPTH * ROWB) + lane * 16;

    for (int si = 0; si < 2; si++) {
        if (si >= nseg) {
            if (tid == 0) g_partial[c * 2 + 1] = 0.0f;   // unused slot := 0
            break;
        }
        const int p      = p0 + si;
        const int seg_lo = (si == 0) ? lo : (p << 9);
        const int seg_hi = (si + 1 == nseg) ? hi : ((p + 1) << 9);
        const int len    = seg_hi - seg_lo;              // <= 148 (< 256)

        // ---- Deterministic compaction of this segment's masked rows ----
        const int m = (tid < len) ? mask[seg_lo + tid] : 0;
        const unsigned bal = __ballot_sync(0xFFFFFFFFu, m != 0);
        if (lane == 0) s_cnt[warp] = __popc(bal);
        __syncthreads();
        int off = 0;
        #pragma unroll
        for (int w = 0; w < 8; w++) if (w < warp) off += s_cnt[w];
        const int n_nz = s_cnt[0] + s_cnt[1] + s_cnt[2] + s_cnt[3]
                       + s_cnt[4] + s_cnt[5] + s_cnt[6] + s_cnt[7];
        if (m != 0)
            s_idx[off + __popc(bal & ((1u << lane) - 1u))] = (short)tid;
        __syncthreads();

        // ---- Sentence slice for pair p, straight from gmem (L2-hot) ----
        const float4* __restrict__ sp4 = (const float4*)(sent + (size_t)p * DD);
        const float4 b0 = __ldg(sp4 + lane +   0);
        const float4 b1 = __ldg(sp4 + lane +  32);
        const float4 b2 = __ldg(sp4 + lane +  64);
        const float4 b3 = __ldg(sp4 + lane +  96);
        const float4 b4 = __ldg(sp4 + lane + 128);
        const float4 b5 = __ldg(sp4 + lane + 160);

        const char* __restrict__ tokseg = (const char*)tok + (size_t)seg_lo * ROWB;

        const int cnt = (n_nz > warp) ? (n_nz - warp + 7) >> 3 : 0;

        #define ISSUE(j)  do {                                               \
            const char* __g = tokseg + (size_t)s_idx[warp + 8*(j)] * ROWB    \
                            + lane * 16;                                     \
            unsigned __s = buf_base + ((j) % DEPTH) * ROWB;                  \
            cp16(__s,          __g);                                         \
            cp16(__s +  512,   __g +  512);                                  \
            cp16(__s + 1024,   __g + 1024);                                  \
            cp16(__s + 1536,   __g + 1536);                                  \
            cp16(__s + 2048,   __g + 2048);                                  \
            cp16(__s + 2560,   __g + 2560);                                  \
            asm volatile("cp.async.commit_group;");                          \
        } while (0)

        if (cnt > 0) ISSUE(0);
        if (cnt > 1) ISSUE(1);

        float acc = 0.0f;
        for (int j = 0; j < cnt; j++) {
            if (j + 2 < cnt)      { ISSUE(j + 2); asm volatile("cp.async.wait_group 2;"); }
            else if (j + 1 < cnt) { asm volatile("cp.async.wait_group 1;"); }
            else                  { asm volatile("cp.async.wait_group 0;"); }

            const unsigned s = buf_base + (j % DEPTH) * ROWB;
            float4 a0 = *(const float4*)__cvta_shared_to_generic(s);
            float4 a1 = *(const float4*)__cvta_shared_to_generic(s +  512);
            float4 a2 = *(const float4*)__cvta_shared_to_generic(s + 1024);
            float4 a3 = *(const float4*)__cvta_shared_to_generic(s + 1536);
            float4 a4 = *(const float4*)__cvta_shared_to_generic(s + 2048);
            float4 a5 = *(const float4*)__cvta_shared_to_generic(s + 2560);
            acc += a0.x*b0.x + a0.y*b0.y + a0.z*b0.z + a0.w*b0.w
                 + a1.x*b1.x + a1.y*b1.y + a1.z*b1.z + a1.w*b1.w
                 + a2.x*b2.x + a2.y*b2.y + a2.z*b2.z + a2.w*b2.w
                 + a3.x*b3.x + a3.y*b3.y + a3.z*b3.z + a3.w*b3.w
                 + a4.x*b4.x + a4.y*b4.y + a4.z*b4.z + a4.w*b4.w
                 + a5.x*b5.x + a5.y*b5.y + a5.z*b5.z + a5.w*b5.w;
        }
        #undef ISSUE

        // ---- Segment reduction -> unique slot (fixed order) ----
        #pragma unroll
        for (int o = 16; o; o >>= 1)
            acc += __shfl_xor_sync(0xFFFFFFFFu, acc, o);
        if (lane == 0) s_acc[warp] = acc;
        __syncthreads();
        if (tid == 0) {
            float t = 0.0f;
            #pragma unroll
            for (int w = 0; w < 8; w++) t += s_acc[w];
            g_partial[c * 2 + si] = t;
        }
        __syncthreads();   // protect s_idx/s_cnt reuse in next segment
    }

    // ---- Completion detection ----
    if (tid == 0) {
        __threadfence();
        unsigned d = atomicAdd(&g_count, 1u);
        *s_flag = (d == GRIDN - 1) ? 1 : 0;
    }
    __syncthreads();

    if (*s_flag) {
        // Last CTA: fixed-order finalize over all slots.
        __threadfence();
        if (tid < NPAIR) {
            float t = 0.0f;
            for (int cc = 0; cc < GRIDN; cc++) {
                const int l  = (int)(((long long)cc * NROWS) / GRIDN);
                const int h  = (int)(((long long)(cc + 1) * NROWS) / GRIDN);
                const int q0 = l >> 9;
                const int q1 = (h - 1) >> 9;
                if (q0 == tid) t += g_partial[cc * 2];
                if (q1 != q0 && q1 == tid) t += g_partial[cc * 2 + 1];
            }
            s_val[tid] = t / (t + 1e-9f);
        }
        __syncthreads();
        if (tid == 0) {
            float r = 0.0f;
            #pragma unroll
            for (int i = 0; i < NPAIR; i++) r += s_val[i];
            *out = r / (float)FF;
            g_count = 0;  // reset for next graph replay
        }
    }
}

extern "C" void kernel_launch(void* const* d_in, const int* in_sizes, int n_in,
                              void* d_out, int out_size) {
    const float* tok  = (const float*)d_in[0];
    const float* sent = (const float*)d_in[1];
    const int*   mask = (const int*)d_in[2];
    float* out = (float*)d_out;

    static int configured = 0;
    if (!configured) {
        cudaFuncSetAttribute(nl_fused_kernel,
                             cudaFuncAttributeMaxDynamicSharedMemorySize,
                             SMEM_BYTES);
        configured = 1;
    }
    nl_fused_kernel<<<GRIDN, 256, SMEM_BYTES>>>(tok, sent, mask, out);
}

// round 14
// speedup vs baseline: 1.7868x; 1.7868x over previous
#include <cuda_runtime.h>
#include <cuda_bf16.h>

// Shapes fixed by reference setup_inputs
#define FF 2
#define BB 64
#define SS 512
#define DD 768
#define ROWB (DD * 4)          // 3072 bytes per row
#define NPAIR (FF * BB)        // 128
#define CHUNK 256              // s-rows per CTA (pair-aligned, long runs)
#define NCHUNK (SS / CHUNK)    // 2
#define GRID (NPAIR * NCHUNK)  // 256 -> 3 CTAs/SM capacity, single wave

#define DEPTH 3
#define BUFS_BYTES (8 * DEPTH * ROWB)    // 73728
#define CTRL_OFF   BUFS_BYTES
#define SMEM_BYTES (BUFS_BYTES + 2048)   // 75776 (x3 = 227328 B/SM)

__device__ float        g_partial[GRID];
__device__ unsigned int g_count = 0;

// cp.async 16B with L2 evict_last cache policy (keep tok resident across replays)
__device__ __forceinline__ void cp16_el(unsigned sdst, const void* gsrc) {
    asm volatile(
        "{\n\t"
        ".reg .b64 pol;\n\t"
        "createpolicy.fractional.L2::evict_last.b64 pol;\n\t"
        "cp.async.cg.shared.global.L2::cache_hint [%0], [%1], 16, pol;\n\t"
        "}" :: "r"(sdst), "l"(gsrc));
}

__global__ __launch_bounds__(256) void nl_fused_kernel(
    const float* __restrict__ tok,
    const float* __restrict__ sent,
    const int* __restrict__ mask,
    float* __restrict__ out)
{
    extern __shared__ char smem[];
    const int fb    = blockIdx.x >> 1;        // pair
    const int chunk = blockIdx.x & 1;
    const int tid   = threadIdx.x;
    const int warp  = tid >> 5;
    const int lane  = tid & 31;
    const int s_begin = chunk * CHUNK;

    short* s_idx = (short*)(smem + CTRL_OFF);          // [CHUNK] = 512 B
    int*   s_cnt = (int*)(smem + CTRL_OFF + 512);      // [8]
    float* s_acc = (float*)(smem + CTRL_OFF + 576);    // [8]
    float* s_val = (float*)(smem + CTRL_OFF + 640);    // [NPAIR]

    // ---- Deterministic compaction: 8 warps x 32-row segments ----
    const int* __restrict__ mrow = mask + (size_t)fb * SS + s_begin;
    const int m = mrow[warp * 32 + lane];
    const unsigned bal = __ballot_sync(0xFFFFFFFFu, m != 0);
    if (lane == 0) s_cnt[warp] = __popc(bal);
    __syncthreads();
    int off = 0;
    #pragma unroll
    for (int w = 0; w < 8; w++) if (w < warp) off += s_cnt[w];
    const int n_nz = s_cnt[0] + s_cnt[1] + s_cnt[2] + s_cnt[3]
                   + s_cnt[4] + s_cnt[5] + s_cnt[6] + s_cnt[7];
    if (m != 0)
        s_idx[off + __popc(bal & ((1u << lane) - 1u))] = (short)(warp * 32 + lane);
    __syncthreads();

    // ---- Sentence slice in registers, straight from gmem (L2-hot) ----
    const float4* __restrict__ sp4 = (const float4*)(sent + (size_t)fb * DD);
    const float4 b0 = __ldg(sp4 + lane +   0);
    const float4 b1 = __ldg(sp4 + lane +  32);
    const float4 b2 = __ldg(sp4 + lane +  64);
    const float4 b3 = __ldg(sp4 + lane +  96);
    const float4 b4 = __ldg(sp4 + lane + 128);
    const float4 b5 = __ldg(sp4 + lane + 160);

    const char* __restrict__ tokbase =
        (const char*)(tok + ((size_t)fb * SS + s_begin) * DD);
    const unsigned buf_base =
        (unsigned)__cvta_generic_to_shared(smem) + warp * (DEPTH * ROWB) + lane * 16;

    // ---- Contiguous per-warp block of the compact list ----
    const int base = n_nz >> 3;
    const int rem  = n_nz & 7;
    const int my_begin = warp * base + ((warp < rem) ? warp : rem);
    const int cnt      = base + (warp < rem ? 1 : 0);

    #define ISSUE(j)  do {                                                   \
        const char* __g = tokbase + (size_t)s_idx[my_begin + (j)] * ROWB     \
                        + lane * 16;                                         \
        unsigned __s = buf_base + ((j) % DEPTH) * ROWB;                      \
        cp16_el(__s,          __g);                                          \
        cp16_el(__s +  512,   __g +  512);                                   \
        cp16_el(__s + 1024,   __g + 1024);                                   \
        cp16_el(__s + 1536,   __g + 1536);                                   \
        cp16_el(__s + 2048,   __g + 2048);                                   \
        cp16_el(__s + 2560,   __g + 2560);                                   \
        asm volatile("cp.async.commit_group;");                              \
    } while (0)

    if (cnt > 0) ISSUE(0);
    if (cnt > 1) ISSUE(1);

    float acc = 0.0f;
    for (int j = 0; j < cnt; j++) {
        if (j + 2 < cnt)      { ISSUE(j + 2); asm volatile("cp.async.wait_group 2;"); }
        else if (j + 1 < cnt) { asm volatile("cp.async.wait_group 1;"); }
        else                  { asm volatile("cp.async.wait_group 0;"); }

        const unsigned s = buf_base + (j % DEPTH) * ROWB;
        float4 a0 = *(const float4*)__cvta_shared_to_generic(s);
        float4 a1 = *(const float4*)__cvta_shared_to_generic(s +  512);
        float4 a2 = *(const float4*)__cvta_shared_to_generic(s + 1024);
        float4 a3 = *(const float4*)__cvta_shared_to_generic(s + 1536);
        float4 a4 = *(const float4*)__cvta_shared_to_generic(s + 2048);
        float4 a5 = *(const float4*)__cvta_shared_to_generic(s + 2560);
        acc += a0.x*b0.x + a0.y*b0.y + a0.z*b0.z + a0.w*b0.w
             + a1.x*b1.x + a1.y*b1.y + a1.z*b1.z + a1.w*b1.w
             + a2.x*b2.x + a2.y*b2.y + a2.z*b2.z + a2.w*b2.w
             + a3.x*b3.x + a3.y*b3.y + a3.z*b3.z + a3.w*b3.w
             + a4.x*b4.x + a4.y*b4.y + a4.z*b4.z + a4.w*b4.w
             + a5.x*b5.x + a5.y*b5.y + a5.z*b5.z + a5.w*b5.w;
    }
    #undef ISSUE

    // ---- Block reduction (fixed order -> deterministic) ----
    #pragma unroll
    for (int o = 16; o; o >>= 1)
        acc += __shfl_xor_sync(0xFFFFFFFFu, acc, o);
    if (lane == 0) s_acc[warp] = acc;
    __syncthreads();

    if (tid == 0) {
        float t = 0.0f;
        #pragma unroll
        for (int w = 0; w < 8; w++) t += s_acc[w];
        g_partial[blockIdx.x] = t;
        __threadfence();
        unsigned int done = atomicAdd(&g_count, 1u);
        s_acc[0] = (done == GRID - 1) ? 1.0f : 0.0f;
    }
    __syncthreads();

    if (s_acc[0] != 0.0f) {
        // Last CTA finalizes: 128 lanes each own one (f,b) pair.
        __threadfence();
        if (tid < NPAIR) {
            float t = 0.0f;
            #pragma unroll
            for (int c = 0; c < NCHUNK; c++)
                t += g_partial[tid * NCHUNK + c];
            s_val[tid] = t / (t + 1e-9f);
        }
        __syncthreads();
        if (tid == 0) {
            float r = 0.0f;
            #pragma unroll
            for (int i = 0; i < NPAIR; i++) r += s_val[i];
            *out = r / (float)FF;
            g_count = 0;  // reset for next graph replay
        }
    }
}

extern "C" void kernel_launch(void* const* d_in, const int* in_sizes, int n_in,
                              void* d_out, int out_size) {
    const float* tok  = (const float*)d_in[0];
    const float* sent = (const float*)d_in[1];
    const int*   mask = (const int*)d_in[2];
    float* out = (float*)d_out;

    static int configured = 0;
    if (!configured) {
        cudaFuncSetAttribute(nl_fused_kernel,
                             cudaFuncAttributeMaxDynamicSharedMemorySize,
                             SMEM_BYTES);
        configured = 1;
    }
    nl_fused_kernel<<<GRID, 256, SMEM_BYTES>>>(tok, sent, mask, out);
}